// round 7
// baseline (speedup 1.0000x reference)
#include <cuda_runtime.h>
#include <math.h>

#define NIMG 8
#define AA 3
#define HH 336
#define WW 336
#define HWSZ (HH*WW)            // 112896
#define MM (AA*HWSZ)            // 338688
#define MM4 (MM/4)              // 84672
#define PRE_K 2000
#define POST_N 1000
#define CAND_CAP 4096
#define MASK_ROWS 2048
#define MASK_WORDS 64
#define NEGV (-1e9f)
#define FULLM 0xffffffffu
#define GRID_FAT 1184           // 148 SMs * 8 blocks -> one wave at 256 thr

// ---------------- scratch (device globals; no allocations) ----------------
__device__ float4             d_scores4[NIMG * MM4];                     // 10.8 MB (linear order)
__device__ __align__(16) unsigned int d_hist[NIMG * 65536];              // 2 MB
__device__ int                d_threshbin[NIMG];
__device__ int                d_candcount[NIMG];
__device__ unsigned long long d_cand[NIMG * CAND_CAP];                   // 256 KB
__device__ float4             d_boxes[NIMG * PRE_K];                     // 256 KB
__device__ float              d_selscore[NIMG * PRE_K];
__device__ float              d_area[NIMG * PRE_K];
__device__ unsigned int       d_maskbits[NIMG * MASK_ROWS * MASK_WORDS]; // 4 MB (lower triangle stays 0)
__device__ unsigned int       d_validmask[NIMG * MASK_WORDS];

// ---------------- K0: zero counters/hist (vectorized, one wave) ----------------
__global__ void k0_zero() {
    int stride = gridDim.x * blockDim.x;
    int t0 = blockIdx.x * blockDim.x + threadIdx.x;
    uint4 z = make_uint4(0u, 0u, 0u, 0u);
    uint4* h4 = (uint4*)d_hist;
    for (int t = t0; t < NIMG * 65536 / 4; t += stride) h4[t] = z;
    if (t0 < NIMG) d_candcount[t0] = 0;
}

// ---------------- K1: sigmoid + store + ordered histogram (float4, 1 wave) ----------------
__global__ void k1_scores(const float4* __restrict__ logits4) {
    int stride = gridDim.x * blockDim.x;
    for (int t = blockIdx.x * blockDim.x + threadIdx.x; t < NIMG * MM4; t += stride) {
        float4 x = logits4[t];
        float4 s;
        s.x = 1.0f / (1.0f + expf(-x.x));
        s.y = 1.0f / (1.0f + expf(-x.y));
        s.z = 1.0f / (1.0f + expf(-x.z));
        s.w = 1.0f / (1.0f + expf(-x.w));
        d_scores4[t] = s;                    // single source of truth for score bits
        unsigned base = (unsigned)(t / MM4) << 16;   // MM % 4 == 0: no image straddle
        atomicAdd(&d_hist[base + ((__float_as_uint(s.x) | 0x80000000u) >> 16)], 1u);
        atomicAdd(&d_hist[base + ((__float_as_uint(s.y) | 0x80000000u) >> 16)], 1u);
        atomicAdd(&d_hist[base + ((__float_as_uint(s.z) | 0x80000000u) >> 16)], 1u);
        atomicAdd(&d_hist[base + ((__float_as_uint(s.w) | 0x80000000u) >> 16)], 1u);
    }
}

// ---------------- K2: per-image rank-PRE_K threshold bin (uint4 sums) ----------------
__global__ void k2_thresh() {
    int n = blockIdx.x;
    int t = threadIdx.x;  // 256
    __shared__ unsigned csum[256];
    __shared__ unsigned bins[256];
    __shared__ int      s_chunk;
    __shared__ unsigned s_cum;
    const uint4* h4 = (const uint4*)(d_hist + (n << 16));
    int warp = t >> 5, lane = t & 31;
    for (int c = warp; c < 256; c += 8) {
        uint4 v0 = h4[c * 64 + lane];
        uint4 v1 = h4[c * 64 + 32 + lane];
        unsigned s = v0.x + v0.y + v0.z + v0.w + v1.x + v1.y + v1.z + v1.w;
#pragma unroll
        for (int o = 16; o; o >>= 1) s += __shfl_down_sync(FULLM, s, o);
        if (lane == 0) csum[c] = s;
    }
    __syncthreads();
    if (t == 0) {
        unsigned cum = 0;
        int chunk = 0;
        for (int c = 255; c >= 0; c--) {
            if (cum + csum[c] >= PRE_K) { chunk = c; break; }
            cum += csum[c];
        }
        s_chunk = chunk;
        s_cum = cum;
    }
    __syncthreads();
    int chunk = s_chunk;
    bins[t] = d_hist[(n << 16) + chunk * 256 + t];
    __syncthreads();
    if (t == 0) {
        unsigned cum = s_cum;
        int thresh = chunk * 256;
        for (int b = 255; b >= 0; b--) {
            cum += bins[b];
            if (cum >= PRE_K) { thresh = chunk * 256 + b; break; }
        }
        d_threshbin[n] = thresh;
    }
}

// ---------------- K3: compact candidate keys (float4, batched atomics) ----------------
__global__ void k3_compact() {
    int stride = gridDim.x * blockDim.x;
    for (int t = blockIdx.x * blockDim.x + threadIdx.x; t < NIMG * MM4; t += stride) {
        float4 s = d_scores4[t];             // identical bits to k1 by construction
        int n = t / MM4;
        int rem = t * 4 - n * MM;
        int thr = d_threshbin[n];
        unsigned u[4];
        u[0] = __float_as_uint(s.x) | 0x80000000u;
        u[1] = __float_as_uint(s.y) | 0x80000000u;
        u[2] = __float_as_uint(s.z) | 0x80000000u;
        u[3] = __float_as_uint(s.w) | 0x80000000u;
        bool p[4];
        int cnt = 0;
#pragma unroll
        for (int c = 0; c < 4; c++) { p[c] = ((int)(u[c] >> 16) >= thr); cnt += p[c]; }
        if (cnt) {
            int pos = atomicAdd(&d_candcount[n], cnt);
#pragma unroll
            for (int c = 0; c < 4; c++) {
                if (p[c]) {
                    if (pos < CAND_CAP) {
                        int a  = (rem + c) / HWSZ;
                        int hw = (rem + c) - a * HWSZ;
                        unsigned f = (unsigned)(hw * AA + a);   // score-order index
                        d_cand[n * CAND_CAP + pos] =
                            ((unsigned long long)u[c] << 32) |
                            (unsigned long long)(0xFFFFFFFFu - f);
                    }
                    pos++;
                }
            }
        }
    }
}

// ---------------- K4: bitonic sort (warp-local mid substages, safe barriers) ----------------
__device__ __forceinline__ void cswp(unsigned long long& a, unsigned long long& b, bool desc) {
    if (desc ? (a < b) : (a > b)) { unsigned long long tmp = a; a = b; b = tmp; }
}

__global__ __launch_bounds__(1024) void k4_sortdecode(const float* __restrict__ anchors,
                                                      const float* __restrict__ breg) {
    __shared__ unsigned long long sm[CAND_CAP];
    int n = blockIdx.x;
    int tid = threadIdx.x;  // 1024
    int cnt = d_candcount[n];
    if (cnt > CAND_CAP) cnt = CAND_CAP;

    // thread owns 4 consecutive elements b..b+3; k=2 and k=4 phases in registers
    int b = tid * 4;
    unsigned long long r0 = (b + 0 < cnt) ? d_cand[n * CAND_CAP + b + 0] : 0ULL;
    unsigned long long r1 = (b + 1 < cnt) ? d_cand[n * CAND_CAP + b + 1] : 0ULL;
    unsigned long long r2 = (b + 2 < cnt) ? d_cand[n * CAND_CAP + b + 2] : 0ULL;
    unsigned long long r3 = (b + 3 < cnt) ? d_cand[n * CAND_CAP + b + 3] : 0ULL;
    cswp(r0, r1, true); cswp(r2, r3, false);          // k=2
    {
        bool d4 = ((b & 4) == 0);                     // k=4
        cswp(r0, r2, d4); cswp(r1, r3, d4);
        cswp(r0, r1, d4); cswp(r2, r3, d4);
    }
    sm[b] = r0; sm[b + 1] = r1; sm[b + 2] = r2; sm[b + 3] = r3;
    __syncthreads();

    for (int k = 8; k <= CAND_CAP; k <<= 1) {
        // cross-warp substages (partner thread differs in bits >= 32): j >= 128
        for (int j = k >> 1; j >= 128; j >>= 1) {
#pragma unroll
            for (int q = 0; q < CAND_CAP / 2048; q++) {   // 2048 pairs, 2 per thread
                int pp = tid + q * 1024;
                int i = ((pp & ~(j - 1)) << 1) | (pp & (j - 1));
                int ixj = i | j;
                bool desc = ((i & k) == 0);
                unsigned long long va = sm[i], vb = sm[ixj];
                if (desc ? (va < vb) : (va > vb)) { sm[i] = vb; sm[ixj] = va; }
            }
            __syncthreads();
        }
        // warp-local substages: j = 64..4 (partner thread = tid ^ (j>>2), same warp)
        bool dk = ((b & k) == 0);
        for (int j = 64; j >= 4; j >>= 1) {
            if (j <= (k >> 1)) {
                if ((b & j) == 0) {
#pragma unroll
                    for (int c = 0; c < 4; c++) {
                        int i = b + c, ixj = i | j;
                        unsigned long long va = sm[i], vb = sm[ixj];
                        if (dk ? (va < vb) : (va > vb)) { sm[i] = vb; sm[ixj] = va; }
                    }
                }
                __syncwarp();
            }
        }
        // fused j=2, j=1 in registers (direction uniform per thread for k>=8)
        r0 = sm[b]; r1 = sm[b + 1]; r2 = sm[b + 2]; r3 = sm[b + 3];
        cswp(r0, r2, dk); cswp(r1, r3, dk);
        cswp(r0, r1, dk); cswp(r2, r3, dk);
        sm[b] = r0; sm[b + 1] = r1; sm[b + 2] = r2; sm[b + 3] = r3;
        __syncthreads();   // phase boundary: next phase reads cross-warp
    }

    const float XCLIP = 4.135166556742356f;  // log(1000/16)
#pragma unroll
    for (int pass = 0; pass < 2; pass++) {
        int r = tid + pass * 1024;
        bool keepf = false;
        if (r < PRE_K) {
            unsigned long long key = sm[r];
            unsigned ub = (unsigned)(key >> 32);
            unsigned sbits = (ub & 0x80000000u) ? (ub ^ 0x80000000u) : ~ub;
            float s = __uint_as_float(sbits);
            unsigned f = 0xFFFFFFFFu - (unsigned)(key & 0xFFFFFFFFull);
            int a  = (int)(f % AA);
            int hw = (int)(f / AA);
            float4 anc = ((const float4*)anchors)[(size_t)n * MM + f];
            const float* rp = breg + ((size_t)n * (AA * 4) + a * 4) * HWSZ + hw;
            float dx = rp[0];
            float dy = rp[HWSZ];
            float dwv = rp[2 * HWSZ];
            float dhv = rp[3 * HWSZ];
            float aw = __fadd_rn(__fsub_rn(anc.z, anc.x), 1.0f);
            float ah = __fadd_rn(__fsub_rn(anc.w, anc.y), 1.0f);
            float cx = __fadd_rn(anc.x, __fmul_rn(0.5f, aw));
            float cy = __fadd_rn(anc.y, __fmul_rn(0.5f, ah));
            dwv = fminf(dwv, XCLIP);
            dhv = fminf(dhv, XCLIP);
            float pcx = __fadd_rn(__fmul_rn(dx, aw), cx);
            float pcy = __fadd_rn(__fmul_rn(dy, ah), cy);
            float pw = __fmul_rn((float)exp((double)dwv), aw);
            float ph = __fmul_rn((float)exp((double)dhv), ah);
            float hpw = __fmul_rn(0.5f, pw);
            float hph = __fmul_rn(0.5f, ph);
            float x1 = __fsub_rn(pcx, hpw);
            float y1 = __fsub_rn(pcy, hph);
            float x2 = __fsub_rn(__fadd_rn(pcx, hpw), 1.0f);
            float y2 = __fsub_rn(__fadd_rn(pcy, hph), 1.0f);
            x1 = fminf(fmaxf(x1, 0.0f), 1332.0f);
            x2 = fminf(fmaxf(x2, 0.0f), 1332.0f);
            y1 = fminf(fmaxf(y1, 0.0f), 799.0f);
            y2 = fminf(fmaxf(y2, 0.0f), 799.0f);
            float ws = __fadd_rn(__fsub_rn(x2, x1), 1.0f);
            float hs = __fadd_rn(__fsub_rn(y2, y1), 1.0f);
            keepf = (ws >= 0.0f) && (hs >= 0.0f);
            d_boxes[n * PRE_K + r] = make_float4(x1, y1, x2, y2);
            d_area[n * PRE_K + r] = __fmul_rn(ws, hs);
            d_selscore[n * PRE_K + r] = keepf ? s : NEGV;
        }
        unsigned bal = __ballot_sync(FULLM, keepf);
        if ((tid & 31) == 0) d_validmask[n * MASK_WORDS + (r >> 5)] = bal;
    }
}

// ---------------- K5: suppression bitmask, UPPER TRIANGLE only ----------------
// Greedy NMS only consults bit j of row i for j decided AFTER i; columns < row's
// own 32-word are never needed (stale zeros OR'd harmlessly in k6).
#define RPB 32
__global__ __launch_bounds__(128) void k5_mask() {
    __shared__ float4 sb[2048];
    __shared__ float  sa[2048];
    const int bpi = (PRE_K + RPB - 1) / RPB;  // 63
    int n  = blockIdx.x / bpi;
    int rb = (blockIdx.x % bpi) * RPB;
    int w0 = rb >> 5;                         // uniform per block (rb multiple of 32)
    int tid = threadIdx.x;  // 128
    for (int i = rb + tid; i < 2048; i += 128) {
        if (i < PRE_K) { sb[i] = d_boxes[n * PRE_K + i]; sa[i] = d_area[n * PRE_K + i]; }
        else           { sb[i] = make_float4(0.f, 0.f, -1.f, -1.f); sa[i] = 1.0f; }
    }
    __syncthreads();
    int warp = tid >> 5, lane = tid & 31;
    int r0 = rb + warp * 8;
    if (r0 >= PRE_K) return;   // whole-warp tail (no further block sync)

    float4 bi[8]; float ai[8];
#pragma unroll
    for (int d = 0; d < 8; d++) { bi[d] = sb[r0 + d]; ai[d] = sa[r0 + d]; }
    unsigned* rowbase = d_maskbits + ((size_t)n * MASK_ROWS + r0) * MASK_WORDS;

    // iou > 0.7  <=>  inter > (0.7/1.7)*(ai+aj)   (areas >= 0 => denom > 0)
    // guard band +-~0.06%; ambiguous pairs fall back to the exact division.
    const float HIC = 0.41200f, LOC = 0.41153f;
    for (int w = w0; w < 64; w++) {
        int j = (w << 5) + lane;
        float4 bj = sb[j];
        float  aj = sa[j];
        unsigned words[8];
#pragma unroll
        for (int d = 0; d < 8; d++) {
            float xx1 = fmaxf(bi[d].x, bj.x);
            float yy1 = fmaxf(bi[d].y, bj.y);
            float xx2 = fminf(bi[d].z, bj.z);
            float yy2 = fminf(bi[d].w, bj.w);
            float iw = fmaxf(__fadd_rn(__fsub_rn(xx2, xx1), 1.0f), 0.0f);
            float ih = fmaxf(__fadd_rn(__fsub_rn(yy2, yy1), 1.0f), 0.0f);
            float inter = __fmul_rn(iw, ih);
            float ssum  = __fadd_rn(ai[d], aj);
            bool sup;
            if (inter > __fmul_rn(HIC, ssum))      sup = true;
            else if (inter < __fmul_rn(LOC, ssum)) sup = false;
            else sup = __fdiv_rn(inter, __fsub_rn(ssum, inter)) > 0.7f;
            words[d] = __ballot_sync(FULLM, sup);
        }
        // parallel store: lane d (d<8) writes row d's word w (SEL chain, 1 STG)
        unsigned v = words[0];
#pragma unroll
        for (int d = 1; d < 8; d++) v = (lane == d) ? words[d] : v;
        if (lane < 8) rowbase[(size_t)lane * MASK_WORDS + w] = v;
    }
}

// ---------------- K6: serial greedy NMS scan, 1 warp per image, depth-2 prefetch ----------------
__device__ __forceinline__ void k6_load_group(const unsigned* __restrict__ maskb, int lane,
                                              int i0, unsigned (&b0)[8], unsigned (&b1)[8]) {
#pragma unroll
    for (int d = 0; d < 8; d++) {
        const unsigned* r = maskb + (size_t)(i0 + d) * MASK_WORDS;
        b0[d] = r[lane];
        b1[d] = r[lane + 32];
    }
}

__device__ __forceinline__ void k6_proc_group(int i0, int lane,
                                              unsigned (&b0)[8], unsigned (&b1)[8],
                                              unsigned& sup0, unsigned& sup1,
                                              unsigned val0, unsigned val1,
                                              int& count, int* list) {
    int Wd = i0 >> 5;             // constant across the 8-row group
    int slot = Wd >> 5;
    int ol = Wd & 31;
    unsigned kb = slot ? sup1 : sup0;
    unsigned kv = slot ? val1 : val0;
    unsigned keep8 = 0;
    int bit0 = i0 & 31;
#pragma unroll
    for (int d = 0; d < 8; d++) {
        unsigned m = 1u << (bit0 + d);
        if ((kv & m) && !(kb & m)) {
            keep8 |= (1u << d);
            kb |= slot ? b1[d] : b0[d];   // owner lane holds word Wd of row i0+d
        }
    }
    keep8 = __shfl_sync(FULLM, keep8, ol);
#pragma unroll
    for (int d = 0; d < 8; d++) {
        if (keep8 & (1u << d)) { sup0 |= b0[d]; sup1 |= b1[d]; }
    }
    if (lane == 0) {
        int c = count;
#pragma unroll
        for (int d = 0; d < 8; d++) {
            if (keep8 & (1u << d)) {
                if (c < POST_N) list[c] = i0 + d;
                c++;
            }
        }
    }
    count += __popc(keep8);
}

__global__ __launch_bounds__(32) void k6_nms(float* __restrict__ out) {
    int n = blockIdx.x;
    int lane = threadIdx.x;
    __shared__ int list[POST_N];
    const unsigned* maskb = d_maskbits + (size_t)n * MASK_ROWS * MASK_WORDS;
    unsigned sup0 = 0, sup1 = 0;
    unsigned val0 = d_validmask[n * MASK_WORDS + lane];
    unsigned val1 = d_validmask[n * MASK_WORDS + 32 + lane];
    int count = 0;
    unsigned A0[8], A1[8], B0[8], B1[8], C0[8], C1[8];

    // depth-2 pipeline: while processing group i0, group i0+16 is loading.
    // max prefetch row = 1992+16+7 = 2015 < MASK_ROWS.
    k6_load_group(maskb, lane, 0, A0, A1);
    k6_load_group(maskb, lane, 8, B0, B1);
    int i0 = 0;
    while (true) {
        k6_load_group(maskb, lane, i0 + 16, C0, C1);
        k6_proc_group(i0, lane, A0, A1, sup0, sup1, val0, val1, count, list);
        i0 += 8;
        if (count >= POST_N || i0 >= PRE_K) break;
        k6_load_group(maskb, lane, i0 + 16, A0, A1);
        k6_proc_group(i0, lane, B0, B1, sup0, sup1, val0, val1, count, list);
        i0 += 8;
        if (count >= POST_N || i0 >= PRE_K) break;
        k6_load_group(maskb, lane, i0 + 16, B0, B1);
        k6_proc_group(i0, lane, C0, C1, sup0, sup1, val0, val1, count, list);
        i0 += 8;
        if (count >= POST_N || i0 >= PRE_K) break;
    }
    __syncwarp();

    float* o = out + (size_t)n * POST_N * 5;
    int cmax = count < POST_N ? count : POST_N;
    for (int r = lane; r < POST_N; r += 32) {
        float v0 = 0.f, v1 = 0.f, v2 = 0.f, v3 = 0.f, v4 = 0.f;
        if (r < cmax) {
            int i = list[r];
            float4 b = d_boxes[n * PRE_K + i];
            v0 = b.x; v1 = b.y; v2 = b.z; v3 = b.w;
            v4 = d_selscore[n * PRE_K + i];
        }
        o[r * 5 + 0] = v0;
        o[r * 5 + 1] = v1;
        o[r * 5 + 2] = v2;
        o[r * 5 + 3] = v3;
        o[r * 5 + 4] = v4;
    }
}

// ---------------- launch ----------------
extern "C" void kernel_launch(void* const* d_in, const int* in_sizes, int n_in,
                              void* d_out, int out_size) {
    const float* anchors = (const float*)d_in[0];   // [8, 338688, 4]
    const float* logits  = (const float*)d_in[1];   // [8, 3, 336, 336]
    const float* breg    = (const float*)d_in[2];   // [8, 12, 336, 336]
    float* out = (float*)d_out;                     // [8, 1000, 5]

    (void)in_sizes; (void)n_in; (void)out_size;

    k0_zero<<<GRID_FAT, 256>>>();
    k1_scores<<<GRID_FAT, 256>>>((const float4*)logits);
    k2_thresh<<<NIMG, 256>>>();
    k3_compact<<<GRID_FAT, 256>>>();
    k4_sortdecode<<<NIMG, 1024>>>(anchors, breg);
    k5_mask<<<NIMG * ((PRE_K + RPB - 1) / RPB), 128>>>();
    k6_nms<<<NIMG, 32>>>(out);
}

// round 8
// speedup vs baseline: 1.0113x; 1.0113x over previous
#include <cuda_runtime.h>
#include <math.h>

#define NIMG 8
#define AA 3
#define HH 336
#define WW 336
#define HWSZ (HH*WW)            // 112896
#define MM (AA*HWSZ)            // 338688
#define PRE_K 2000
#define POST_N 1000
#define CAND_CAP 4096
#define MASK_ROWS 2048
#define MASK_WORDS 64
#define NEGV (-1e9f)
#define FULLM 0xffffffffu
#define GRID_FAT 1184           // 148 SMs * 8 blocks -> one wave at 256 thr

// ---------------- scratch (device globals; no allocations) ----------------
// Invariant: d_hist and d_candcount are ZERO at the start of every replay
// (.bss-zero initially; k3 re-zeroes d_hist, k4 re-zeroes d_candcount).
__device__ float              d_scores[NIMG * MM];                       // 10.8 MB (linear order)
__device__ unsigned int       d_hist[NIMG * 65536];                      // 2 MB
__device__ int                d_threshbin[NIMG];
__device__ int                d_candcount[NIMG];
__device__ unsigned long long d_cand[NIMG * CAND_CAP];                   // 256 KB
__device__ float4             d_boxes[NIMG * PRE_K];                     // 256 KB
__device__ float              d_selscore[NIMG * PRE_K];
__device__ float              d_area[NIMG * PRE_K];
__device__ unsigned int       d_maskbits[NIMG * MASK_ROWS * MASK_WORDS]; // 4 MB
__device__ unsigned int       d_validmask[NIMG * MASK_WORDS];

// ---------------- K1: sigmoid + store + ordered histogram (coalesced, 1 wave) ----------------
__global__ void k1_scores(const float* __restrict__ logits) {
    int stride = gridDim.x * blockDim.x;
    for (int t = blockIdx.x * blockDim.x + threadIdx.x; t < NIMG * MM; t += stride) {
        float x = logits[t];                 // linear = fully coalesced
        float s = 1.0f / (1.0f + expf(-x));
        d_scores[t] = s;                     // single source of truth for score bits
        int n = t / MM;
        unsigned u = __float_as_uint(s) | 0x80000000u;  // s >= 0 always
        atomicAdd(&d_hist[(n << 16) + (u >> 16)], 1u);
    }
}

// ---------------- K2: per-image rank-PRE_K threshold bin ----------------
__global__ void k2_thresh() {
    int n = blockIdx.x;
    int t = threadIdx.x;  // 256
    __shared__ unsigned csum[256];
    __shared__ unsigned bins[256];
    __shared__ int      s_chunk;
    __shared__ unsigned s_cum;
    const unsigned* h = d_hist + (n << 16);
    int warp = t >> 5, lane = t & 31;
    for (int c = warp; c < 256; c += 8) {
        unsigned s = 0;
#pragma unroll
        for (int k = 0; k < 8; k++) s += h[c * 256 + lane + k * 32];  // coalesced
#pragma unroll
        for (int o = 16; o; o >>= 1) s += __shfl_down_sync(FULLM, s, o);
        if (lane == 0) csum[c] = s;
    }
    __syncthreads();
    if (t == 0) {
        unsigned cum = 0;
        int chunk = 0;
        for (int c = 255; c >= 0; c--) {
            if (cum + csum[c] >= PRE_K) { chunk = c; break; }
            cum += csum[c];
        }
        s_chunk = chunk;
        s_cum = cum;
    }
    __syncthreads();
    int chunk = s_chunk;
    bins[t] = h[chunk * 256 + t];
    __syncthreads();
    if (t == 0) {
        unsigned cum = s_cum;
        int thresh = chunk * 256;
        for (int b = 255; b >= 0; b--) {
            cum += bins[b];
            if (cum >= PRE_K) { thresh = chunk * 256 + b; break; }
        }
        d_threshbin[n] = thresh;
    }
}

// ---------------- K3: compact candidate keys + re-zero hist for next replay ----------------
__global__ void k3_compact() {
    int stride = gridDim.x * blockDim.x;
    int t0 = blockIdx.x * blockDim.x + threadIdx.x;
    for (int t = t0; t < NIMG * MM; t += stride) {
        float s = d_scores[t];               // identical bits to k1 by construction
        int n = t / MM;
        int rem = t - n * MM;
        unsigned u = __float_as_uint(s) | 0x80000000u;
        if ((int)(u >> 16) >= d_threshbin[n]) {
            int a  = rem / HWSZ;
            int hw = rem - a * HWSZ;
            unsigned f = (unsigned)(hw * AA + a);   // score-order index
            int pos = atomicAdd(&d_candcount[n], 1);
            if (pos < CAND_CAP) {
                d_cand[n * CAND_CAP + pos] =
                    ((unsigned long long)u << 32) | (unsigned long long)(0xFFFFFFFFu - f);
            }
        }
    }
    // hist was consumed by k2; zero it here so the next replay starts clean
    for (int t = t0; t < NIMG * 65536; t += stride) d_hist[t] = 0u;
}

// ---------------- K4: adaptive-length bitonic sort + decode top-2000 ----------------
__global__ __launch_bounds__(1024) void k4_sortdecode(const float* __restrict__ anchors,
                                                      const float* __restrict__ breg) {
    __shared__ unsigned long long sm[CAND_CAP];
    int n = blockIdx.x;
    int tid = threadIdx.x;  // 1024
    int cnt = d_candcount[n];
    if (cnt > CAND_CAP) cnt = CAND_CAP;
    // sort length: 2048 covers the common case (threshold bin ~5 wide); 4096 fallback
    int L = (cnt <= 2048) ? 2048 : CAND_CAP;
    for (int i = tid; i < L; i += 1024)
        sm[i] = (i < cnt) ? d_cand[n * CAND_CAP + i] : 0ULL;
    __syncthreads();
    if (tid == 0) d_candcount[n] = 0;   // all threads read cnt before this barrier

    // bitonic sort over L elements, descending — __syncthreads every substage
    for (int k = 2; k <= L; k <<= 1) {
        for (int j = k >> 1; j > 0; j >>= 1) {
            for (int i = tid; i < L; i += 1024) {
                int ixj = i ^ j;
                if (ixj > i) {
                    unsigned long long va = sm[i], vb = sm[ixj];
                    bool desc = ((i & k) == 0);
                    if (desc ? (va < vb) : (va > vb)) { sm[i] = vb; sm[ixj] = va; }
                }
            }
            __syncthreads();
        }
    }

    const float XCLIP = 4.135166556742356f;  // log(1000/16)
#pragma unroll
    for (int pass = 0; pass < 2; pass++) {
        int r = tid + pass * 1024;
        bool keepf = false;
        if (r < PRE_K) {
            unsigned long long key = sm[r];
            unsigned ub = (unsigned)(key >> 32);
            unsigned sbits = (ub & 0x80000000u) ? (ub ^ 0x80000000u) : ~ub;
            float s = __uint_as_float(sbits);
            unsigned f = 0xFFFFFFFFu - (unsigned)(key & 0xFFFFFFFFull);
            int a  = (int)(f % AA);
            int hw = (int)(f / AA);
            float4 anc = ((const float4*)anchors)[(size_t)n * MM + f];
            const float* rp = breg + ((size_t)n * (AA * 4) + a * 4) * HWSZ + hw;
            float dx = rp[0];
            float dy = rp[HWSZ];
            float dwv = rp[2 * HWSZ];
            float dhv = rp[3 * HWSZ];
            float aw = __fadd_rn(__fsub_rn(anc.z, anc.x), 1.0f);
            float ah = __fadd_rn(__fsub_rn(anc.w, anc.y), 1.0f);
            float cx = __fadd_rn(anc.x, __fmul_rn(0.5f, aw));
            float cy = __fadd_rn(anc.y, __fmul_rn(0.5f, ah));
            dwv = fminf(dwv, XCLIP);
            dhv = fminf(dhv, XCLIP);
            float pcx = __fadd_rn(__fmul_rn(dx, aw), cx);
            float pcy = __fadd_rn(__fmul_rn(dy, ah), cy);
            float pw = __fmul_rn((float)exp((double)dwv), aw);
            float ph = __fmul_rn((float)exp((double)dhv), ah);
            float hpw = __fmul_rn(0.5f, pw);
            float hph = __fmul_rn(0.5f, ph);
            float x1 = __fsub_rn(pcx, hpw);
            float y1 = __fsub_rn(pcy, hph);
            float x2 = __fsub_rn(__fadd_rn(pcx, hpw), 1.0f);
            float y2 = __fsub_rn(__fadd_rn(pcy, hph), 1.0f);
            x1 = fminf(fmaxf(x1, 0.0f), 1332.0f);
            x2 = fminf(fmaxf(x2, 0.0f), 1332.0f);
            y1 = fminf(fmaxf(y1, 0.0f), 799.0f);
            y2 = fminf(fmaxf(y2, 0.0f), 799.0f);
            float ws = __fadd_rn(__fsub_rn(x2, x1), 1.0f);
            float hs = __fadd_rn(__fsub_rn(y2, y1), 1.0f);
            keepf = (ws >= 0.0f) && (hs >= 0.0f);
            d_boxes[n * PRE_K + r] = make_float4(x1, y1, x2, y2);
            d_area[n * PRE_K + r] = __fmul_rn(ws, hs);
            d_selscore[n * PRE_K + r] = keepf ? s : NEGV;
        }
        unsigned bal = __ballot_sync(FULLM, keepf);
        if ((tid & 31) == 0) d_validmask[n * MASK_WORDS + (r >> 5)] = bal;
    }
}

// ---------------- K5: 2000x2000 suppression bitmask (reg rows, no div) ----------------
#define RPB 32
__global__ __launch_bounds__(128) void k5_mask() {
    __shared__ float4 sb[2048];
    __shared__ float  sa[2048];
    const int bpi = (PRE_K + RPB - 1) / RPB;  // 63
    int n  = blockIdx.x / bpi;
    int rb = (blockIdx.x % bpi) * RPB;
    int tid = threadIdx.x;  // 128
    for (int i = tid; i < 2048; i += 128) {
        if (i < PRE_K) { sb[i] = d_boxes[n * PRE_K + i]; sa[i] = d_area[n * PRE_K + i]; }
        else           { sb[i] = make_float4(0.f, 0.f, -1.f, -1.f); sa[i] = 1.0f; }
    }
    __syncthreads();
    int warp = tid >> 5, lane = tid & 31;
    int r0 = rb + warp * 8;
    if (r0 >= PRE_K) return;   // whole-warp tail (no further block sync)

    float4 bi[8]; float ai[8];
#pragma unroll
    for (int d = 0; d < 8; d++) { bi[d] = sb[r0 + d]; ai[d] = sa[r0 + d]; }
    unsigned* rowbase = d_maskbits + ((size_t)n * MASK_ROWS + r0) * MASK_WORDS;

    // iou > 0.7  <=>  inter > (0.7/1.7)*(ai+aj)   (areas >= 0 => denom > 0)
    // guard band +-~0.06%; ambiguous pairs fall back to the exact division.
    const float HIC = 0.41200f, LOC = 0.41153f;
    for (int w = 0; w < 64; w++) {
        int j = (w << 5) + lane;
        float4 bj = sb[j];
        float  aj = sa[j];
        unsigned words[8];
#pragma unroll
        for (int d = 0; d < 8; d++) {
            float xx1 = fmaxf(bi[d].x, bj.x);
            float yy1 = fmaxf(bi[d].y, bj.y);
            float xx2 = fminf(bi[d].z, bj.z);
            float yy2 = fminf(bi[d].w, bj.w);
            float iw = fmaxf(__fadd_rn(__fsub_rn(xx2, xx1), 1.0f), 0.0f);
            float ih = fmaxf(__fadd_rn(__fsub_rn(yy2, yy1), 1.0f), 0.0f);
            float inter = __fmul_rn(iw, ih);
            float ssum  = __fadd_rn(ai[d], aj);
            bool sup;
            if (inter > __fmul_rn(HIC, ssum))      sup = true;
            else if (inter < __fmul_rn(LOC, ssum)) sup = false;
            else sup = __fdiv_rn(inter, __fsub_rn(ssum, inter)) > 0.7f;
            words[d] = __ballot_sync(FULLM, sup);
        }
        if (lane == 0) {
#pragma unroll
            for (int d = 0; d < 8; d++) rowbase[(size_t)d * MASK_WORDS + w] = words[d];
        }
    }
}

// ---------------- K6: serial greedy NMS scan, 1 warp per image ----------------
__device__ __forceinline__ void k6_load_group(const unsigned* __restrict__ maskb, int lane,
                                              int i0, unsigned (&b0)[8], unsigned (&b1)[8]) {
#pragma unroll
    for (int d = 0; d < 8; d++) {
        const unsigned* r = maskb + (size_t)(i0 + d) * MASK_WORDS;
        b0[d] = r[lane];
        b1[d] = r[lane + 32];
    }
}

__device__ __forceinline__ void k6_proc_group(int i0, int lane,
                                              unsigned (&b0)[8], unsigned (&b1)[8],
                                              unsigned& sup0, unsigned& sup1,
                                              unsigned val0, unsigned val1,
                                              int& count, int* list) {
    int Wd = i0 >> 5;             // constant across the 8-row group
    int slot = Wd >> 5;
    int ol = Wd & 31;
    unsigned kb = slot ? sup1 : sup0;
    unsigned kv = slot ? val1 : val0;
    unsigned keep8 = 0;
    int bit0 = i0 & 31;
#pragma unroll
    for (int d = 0; d < 8; d++) {
        unsigned m = 1u << (bit0 + d);
        if ((kv & m) && !(kb & m)) {
            keep8 |= (1u << d);
            kb |= slot ? b1[d] : b0[d];   // owner lane holds word Wd of row i0+d
        }
    }
    keep8 = __shfl_sync(FULLM, keep8, ol);
#pragma unroll
    for (int d = 0; d < 8; d++) {
        if (keep8 & (1u << d)) { sup0 |= b0[d]; sup1 |= b1[d]; }
    }
    if (lane == 0) {
        int c = count;
#pragma unroll
        for (int d = 0; d < 8; d++) {
            if (keep8 & (1u << d)) {
                if (c < POST_N) list[c] = i0 + d;
                c++;
            }
        }
    }
    count += __popc(keep8);
}

__global__ __launch_bounds__(32) void k6_nms(float* __restrict__ out) {
    int n = blockIdx.x;
    int lane = threadIdx.x;
    __shared__ int list[POST_N];
    const unsigned* maskb = d_maskbits + (size_t)n * MASK_ROWS * MASK_WORDS;
    unsigned sup0 = 0, sup1 = 0;
    unsigned val0 = d_validmask[n * MASK_WORDS + lane];
    unsigned val1 = d_validmask[n * MASK_WORDS + 32 + lane];
    int count = 0;
    unsigned A0[8], A1[8], B0[8], B1[8];

    k6_load_group(maskb, lane, 0, A0, A1);
    int i0 = 0;
    while (true) {
        k6_load_group(maskb, lane, i0 + 8, B0, B1);   // prefetch (rows < 2048, padded)
        k6_proc_group(i0, lane, A0, A1, sup0, sup1, val0, val1, count, list);
        i0 += 8;
        if (count >= POST_N || i0 >= PRE_K) break;
        k6_load_group(maskb, lane, i0 + 8, A0, A1);
        k6_proc_group(i0, lane, B0, B1, sup0, sup1, val0, val1, count, list);
        i0 += 8;
        if (count >= POST_N || i0 >= PRE_K) break;
    }
    __syncwarp();

    float* o = out + (size_t)n * POST_N * 5;
    int cmax = count < POST_N ? count : POST_N;
    for (int r = lane; r < POST_N; r += 32) {
        float v0 = 0.f, v1 = 0.f, v2 = 0.f, v3 = 0.f, v4 = 0.f;
        if (r < cmax) {
            int i = list[r];
            float4 b = d_boxes[n * PRE_K + i];
            v0 = b.x; v1 = b.y; v2 = b.z; v3 = b.w;
            v4 = d_selscore[n * PRE_K + i];
        }
        o[r * 5 + 0] = v0;
        o[r * 5 + 1] = v1;
        o[r * 5 + 2] = v2;
        o[r * 5 + 3] = v3;
        o[r * 5 + 4] = v4;
    }
}

// ---------------- launch ----------------
extern "C" void kernel_launch(void* const* d_in, const int* in_sizes, int n_in,
                              void* d_out, int out_size) {
    const float* anchors = (const float*)d_in[0];   // [8, 338688, 4]
    const float* logits  = (const float*)d_in[1];   // [8, 3, 336, 336]
    const float* breg    = (const float*)d_in[2];   // [8, 12, 336, 336]
    float* out = (float*)d_out;                     // [8, 1000, 5]

    (void)in_sizes; (void)n_in; (void)out_size;

    k1_scores<<<GRID_FAT, 256>>>(logits);
    k2_thresh<<<NIMG, 256>>>();
    k3_compact<<<GRID_FAT, 256>>>();
    k4_sortdecode<<<NIMG, 1024>>>(anchors, breg);
    k5_mask<<<NIMG * ((PRE_K + RPB - 1) / RPB), 128>>>();
    k6_nms<<<NIMG, 32>>>(out);
}

// round 12
// speedup vs baseline: 1.1188x; 1.1063x over previous
#include <cuda_runtime.h>
#include <math.h>

#define NIMG 8
#define AA 3
#define HH 336
#define WW 336
#define HWSZ (HH*WW)            // 112896
#define MM (AA*HWSZ)            // 338688
#define PRE_K 2000
#define POST_N 1000
#define CAND_CAP 4096
#define MASK_ROWS 2048
#define MASK_WORDS 64
#define NEGV (-1e9f)
#define FULLM 0xffffffffu
#define GRID_FAT 1184           // 148 SMs * 8 blocks -> one wave at 256 thr

// ---------------- scratch (device globals; no allocations) ----------------
// Invariant: d_hist and d_candcount are ZERO at the start of every replay
// (.bss-zero initially; k3 re-zeroes d_hist, k4 re-zeroes d_candcount).
__device__ float              d_scores[NIMG * MM];                       // 10.8 MB (linear order)
__device__ unsigned int       d_hist[NIMG * 65536];                      // 2 MB
__device__ int                d_threshbin[NIMG];
__device__ int                d_candcount[NIMG];
__device__ unsigned long long d_cand[NIMG * CAND_CAP];                   // 256 KB
__device__ float4             d_boxes[NIMG * PRE_K];                     // 256 KB
__device__ float              d_selscore[NIMG * PRE_K];
__device__ float              d_area[NIMG * PRE_K];
__device__ unsigned int       d_maskbits[NIMG * MASK_ROWS * MASK_WORDS]; // 4 MB
__device__ unsigned int       d_validmask[NIMG * MASK_WORDS];

// ---------------- K1: sigmoid + store + ordered histogram (coalesced, 1 wave) ----------------
__global__ void k1_scores(const float* __restrict__ logits) {
    int stride = gridDim.x * blockDim.x;
    for (int t = blockIdx.x * blockDim.x + threadIdx.x; t < NIMG * MM; t += stride) {
        float x = logits[t];                 // linear = fully coalesced
        float s = 1.0f / (1.0f + expf(-x));
        d_scores[t] = s;                     // single source of truth for score bits
        int n = t / MM;
        unsigned u = __float_as_uint(s) | 0x80000000u;  // s >= 0 always
        atomicAdd(&d_hist[(n << 16) + (u >> 16)], 1u);
    }
}

// ---------------- K2: per-image rank-PRE_K threshold bin ----------------
__global__ void k2_thresh() {
    int n = blockIdx.x;
    int t = threadIdx.x;  // 256
    __shared__ unsigned csum[256];
    __shared__ unsigned bins[256];
    __shared__ int      s_chunk;
    __shared__ unsigned s_cum;
    const unsigned* h = d_hist + (n << 16);
    int warp = t >> 5, lane = t & 31;
    for (int c = warp; c < 256; c += 8) {
        unsigned s = 0;
#pragma unroll
        for (int k = 0; k < 8; k++) s += h[c * 256 + lane + k * 32];  // coalesced
#pragma unroll
        for (int o = 16; o; o >>= 1) s += __shfl_down_sync(FULLM, s, o);
        if (lane == 0) csum[c] = s;
    }
    __syncthreads();
    if (t == 0) {
        unsigned cum = 0;
        int chunk = 0;
        for (int c = 255; c >= 0; c--) {
            if (cum + csum[c] >= PRE_K) { chunk = c; break; }
            cum += csum[c];
        }
        s_chunk = chunk;
        s_cum = cum;
    }
    __syncthreads();
    int chunk = s_chunk;
    bins[t] = h[chunk * 256 + t];
    __syncthreads();
    if (t == 0) {
        unsigned cum = s_cum;
        int thresh = chunk * 256;
        for (int b = 255; b >= 0; b--) {
            cum += bins[b];
            if (cum >= PRE_K) { thresh = chunk * 256 + b; break; }
        }
        d_threshbin[n] = thresh;
    }
}

// ---------------- K3: compact candidate keys + re-zero hist for next replay ----------------
__global__ void k3_compact() {
    int stride = gridDim.x * blockDim.x;
    int t0 = blockIdx.x * blockDim.x + threadIdx.x;
    for (int t = t0; t < NIMG * MM; t += stride) {
        float s = d_scores[t];               // identical bits to k1 by construction
        int n = t / MM;
        int rem = t - n * MM;
        unsigned u = __float_as_uint(s) | 0x80000000u;
        if ((int)(u >> 16) >= d_threshbin[n]) {
            int a  = rem / HWSZ;
            int hw = rem - a * HWSZ;
            unsigned f = (unsigned)(hw * AA + a);   // score-order index
            int pos = atomicAdd(&d_candcount[n], 1);
            if (pos < CAND_CAP) {
                d_cand[n * CAND_CAP + pos] =
                    ((unsigned long long)u << 32) | (unsigned long long)(0xFFFFFFFFu - f);
            }
        }
    }
    // hist was consumed by k2; zero it here so the next replay starts clean
    for (int t = t0; t < NIMG * 65536; t += stride) d_hist[t] = 0u;
}

// ---------------- K4: register/shuffle bitonic sort + decode top-2000 ----------------
__device__ __forceinline__ void cswp(unsigned long long& a, unsigned long long& b, bool desc) {
    if (desc ? (a < b) : (a > b)) { unsigned long long tmp = a; a = b; b = tmp; }
}

__global__ __launch_bounds__(1024) void k4_sortdecode(const float* __restrict__ anchors,
                                                      const float* __restrict__ breg) {
    __shared__ unsigned long long sm[CAND_CAP];
    int n = blockIdx.x;
    int tid = threadIdx.x;  // 1024
    int cnt = d_candcount[n];
    if (cnt > CAND_CAP) cnt = CAND_CAP;
    __syncthreads();                    // all threads read cnt ...
    if (tid == 0) d_candcount[n] = 0;   // ... before reset for next replay

    if (cnt <= 2048) {
        // ---- fast path: 2048-element bitonic, thread t owns elements 2t, 2t+1 ----
        unsigned long long e0 = (2 * tid     < cnt) ? d_cand[n * CAND_CAP + 2 * tid]     : 0ULL;
        unsigned long long e1 = (2 * tid + 1 < cnt) ? d_cand[n * CAND_CAP + 2 * tid + 1] : 0ULL;

        for (int k = 2; k <= 2048; k <<= 1) {
            bool desc = ((tid & (k >> 1)) == 0);   // == ((i & k) == 0) for i = 2t, 2t+1
            int j = k >> 1;
            if (j >= 64) {
                // cross-warp substages in shared (j = k/2 .. 64)
                sm[2 * tid] = e0; sm[2 * tid + 1] = e1;
                __syncthreads();
                for (; j >= 64; j >>= 1) {
                    int i = ((tid & ~(j - 1)) << 1) | (tid & (j - 1));
                    int ixj = i | j;
                    bool d2 = ((i & k) == 0);
                    unsigned long long va = sm[i], vb = sm[ixj];
                    if (d2 ? (va < vb) : (va > vb)) { sm[i] = vb; sm[ixj] = va; }
                    __syncthreads();
                }
                e0 = sm[2 * tid]; e1 = sm[2 * tid + 1];
            }
            // warp-local substages via shuffle (j = 32 .. 2); lane xor = j/2 <= 16
            for (; j >= 2; j >>= 1) {
                int lx = j >> 1;
                unsigned long long p0 = __shfl_xor_sync(FULLM, e0, lx);
                unsigned long long p1 = __shfl_xor_sync(FULLM, e1, lx);
                bool low = ((tid & lx) == 0);
                bool keepmax = (low == desc);
                e0 = keepmax ? (e0 > p0 ? e0 : p0) : (e0 < p0 ? e0 : p0);
                e1 = keepmax ? (e1 > p1 ? e1 : p1) : (e1 < p1 ? e1 : p1);
            }
            // j == 1: in-register
            cswp(e0, e1, desc);
        }
        sm[2 * tid] = e0; sm[2 * tid + 1] = e1;
        __syncthreads();
    } else {
        // ---- rare fallback: full 4096 shared bitonic (uniform branch per block) ----
        for (int i = tid; i < CAND_CAP; i += 1024)
            sm[i] = (i < cnt) ? d_cand[n * CAND_CAP + i] : 0ULL;
        __syncthreads();
        for (int k = 2; k <= CAND_CAP; k <<= 1) {
            for (int j = k >> 1; j > 0; j >>= 1) {
                for (int i = tid; i < CAND_CAP; i += 1024) {
                    int ixj = i ^ j;
                    if (ixj > i) {
                        unsigned long long va = sm[i], vb = sm[ixj];
                        bool desc = ((i & k) == 0);
                        if (desc ? (va < vb) : (va > vb)) { sm[i] = vb; sm[ixj] = va; }
                    }
                }
                __syncthreads();
            }
        }
    }

    const float XCLIP = 4.135166556742356f;  // log(1000/16)
#pragma unroll
    for (int pass = 0; pass < 2; pass++) {
        int r = tid + pass * 1024;
        bool keepf = false;
        if (r < PRE_K) {
            unsigned long long key = sm[r];
            unsigned ub = (unsigned)(key >> 32);
            unsigned sbits = (ub & 0x80000000u) ? (ub ^ 0x80000000u) : ~ub;
            float s = __uint_as_float(sbits);
            unsigned f = 0xFFFFFFFFu - (unsigned)(key & 0xFFFFFFFFull);
            int a  = (int)(f % AA);
            int hw = (int)(f / AA);
            float4 anc = ((const float4*)anchors)[(size_t)n * MM + f];
            const float* rp = breg + ((size_t)n * (AA * 4) + a * 4) * HWSZ + hw;
            float dx = rp[0];
            float dy = rp[HWSZ];
            float dwv = rp[2 * HWSZ];
            float dhv = rp[3 * HWSZ];
            float aw = __fadd_rn(__fsub_rn(anc.z, anc.x), 1.0f);
            float ah = __fadd_rn(__fsub_rn(anc.w, anc.y), 1.0f);
            float cx = __fadd_rn(anc.x, __fmul_rn(0.5f, aw));
            float cy = __fadd_rn(anc.y, __fmul_rn(0.5f, ah));
            dwv = fminf(dwv, XCLIP);
            dhv = fminf(dhv, XCLIP);
            float pcx = __fadd_rn(__fmul_rn(dx, aw), cx);
            float pcy = __fadd_rn(__fmul_rn(dy, ah), cy);
            float pw = __fmul_rn((float)exp((double)dwv), aw);
            float ph = __fmul_rn((float)exp((double)dhv), ah);
            float hpw = __fmul_rn(0.5f, pw);
            float hph = __fmul_rn(0.5f, ph);
            float x1 = __fsub_rn(pcx, hpw);
            float y1 = __fsub_rn(pcy, hph);
            float x2 = __fsub_rn(__fadd_rn(pcx, hpw), 1.0f);
            float y2 = __fsub_rn(__fadd_rn(pcy, hph), 1.0f);
            x1 = fminf(fmaxf(x1, 0.0f), 1332.0f);
            x2 = fminf(fmaxf(x2, 0.0f), 1332.0f);
            y1 = fminf(fmaxf(y1, 0.0f), 799.0f);
            y2 = fminf(fmaxf(y2, 0.0f), 799.0f);
            float ws = __fadd_rn(__fsub_rn(x2, x1), 1.0f);
            float hs = __fadd_rn(__fsub_rn(y2, y1), 1.0f);
            keepf = (ws >= 0.0f) && (hs >= 0.0f);
            d_boxes[n * PRE_K + r] = make_float4(x1, y1, x2, y2);
            d_area[n * PRE_K + r] = __fmul_rn(ws, hs);
            d_selscore[n * PRE_K + r] = keepf ? s : NEGV;
        }
        unsigned bal = __ballot_sync(FULLM, keepf);
        if ((tid & 31) == 0) d_validmask[n * MASK_WORDS + (r >> 5)] = bal;
    }
}

// ---------------- K5: 2000x2000 suppression bitmask (reg rows, no div) ----------------
#define RPB 32
__global__ __launch_bounds__(128) void k5_mask() {
    __shared__ float4 sb[2048];
    __shared__ float  sa[2048];
    const int bpi = (PRE_K + RPB - 1) / RPB;  // 63
    int n  = blockIdx.x / bpi;
    int rb = (blockIdx.x % bpi) * RPB;
    int tid = threadIdx.x;  // 128
    for (int i = tid; i < 2048; i += 128) {
        if (i < PRE_K) { sb[i] = d_boxes[n * PRE_K + i]; sa[i] = d_area[n * PRE_K + i]; }
        else           { sb[i] = make_float4(0.f, 0.f, -1.f, -1.f); sa[i] = 1.0f; }
    }
    __syncthreads();
    int warp = tid >> 5, lane = tid & 31;
    int r0 = rb + warp * 8;
    if (r0 >= PRE_K) return;   // whole-warp tail (no further block sync)

    float4 bi[8]; float ai[8];
#pragma unroll
    for (int d = 0; d < 8; d++) { bi[d] = sb[r0 + d]; ai[d] = sa[r0 + d]; }
    unsigned* rowbase = d_maskbits + ((size_t)n * MASK_ROWS + r0) * MASK_WORDS;

    // iou > 0.7  <=>  inter > (0.7/1.7)*(ai+aj)   (areas >= 0 => denom > 0)
    // guard band +-~0.06%; ambiguous pairs fall back to the exact division.
    const float HIC = 0.41200f, LOC = 0.41153f;
    for (int w = 0; w < 64; w++) {
        int j = (w << 5) + lane;
        float4 bj = sb[j];
        float  aj = sa[j];
        unsigned words[8];
#pragma unroll
        for (int d = 0; d < 8; d++) {
            float xx1 = fmaxf(bi[d].x, bj.x);
            float yy1 = fmaxf(bi[d].y, bj.y);
            float xx2 = fminf(bi[d].z, bj.z);
            float yy2 = fminf(bi[d].w, bj.w);
            float iw = fmaxf(__fadd_rn(__fsub_rn(xx2, xx1), 1.0f), 0.0f);
            float ih = fmaxf(__fadd_rn(__fsub_rn(yy2, yy1), 1.0f), 0.0f);
            float inter = __fmul_rn(iw, ih);
            float ssum  = __fadd_rn(ai[d], aj);
            bool sup;
            if (inter > __fmul_rn(HIC, ssum))      sup = true;
            else if (inter < __fmul_rn(LOC, ssum)) sup = false;
            else sup = __fdiv_rn(inter, __fsub_rn(ssum, inter)) > 0.7f;
            words[d] = __ballot_sync(FULLM, sup);
        }
        if (lane == 0) {
#pragma unroll
            for (int d = 0; d < 8; d++) rowbase[(size_t)d * MASK_WORDS + w] = words[d];
        }
    }
}

// ---------------- K6: serial greedy NMS scan, 1 warp per image ----------------
__device__ __forceinline__ void k6_load_group(const unsigned* __restrict__ maskb, int lane,
                                              int i0, unsigned (&b0)[8], unsigned (&b1)[8]) {
#pragma unroll
    for (int d = 0; d < 8; d++) {
        const unsigned* r = maskb + (size_t)(i0 + d) * MASK_WORDS;
        b0[d] = r[lane];
        b1[d] = r[lane + 32];
    }
}

__device__ __forceinline__ void k6_proc_group(int i0, int lane,
                                              unsigned (&b0)[8], unsigned (&b1)[8],
                                              unsigned& sup0, unsigned& sup1,
                                              unsigned val0, unsigned val1,
                                              int& count, int* list) {
    int Wd = i0 >> 5;             // constant across the 8-row group
    int slot = Wd >> 5;
    int ol = Wd & 31;
    unsigned kb = slot ? sup1 : sup0;
    unsigned kv = slot ? val1 : val0;
    unsigned keep8 = 0;
    int bit0 = i0 & 31;
#pragma unroll
    for (int d = 0; d < 8; d++) {
        unsigned m = 1u << (bit0 + d);
        if ((kv & m) && !(kb & m)) {
            keep8 |= (1u << d);
            kb |= slot ? b1[d] : b0[d];   // owner lane holds word Wd of row i0+d
        }
    }
    keep8 = __shfl_sync(FULLM, keep8, ol);
#pragma unroll
    for (int d = 0; d < 8; d++) {
        if (keep8 & (1u << d)) { sup0 |= b0[d]; sup1 |= b1[d]; }
    }
    if (lane == 0) {
        int c = count;
#pragma unroll
        for (int d = 0; d < 8; d++) {
            if (keep8 & (1u << d)) {
                if (c < POST_N) list[c] = i0 + d;
                c++;
            }
        }
    }
    count += __popc(keep8);
}

__global__ __launch_bounds__(32) void k6_nms(float* __restrict__ out) {
    int n = blockIdx.x;
    int lane = threadIdx.x;
    __shared__ int list[POST_N];
    const unsigned* maskb = d_maskbits + (size_t)n * MASK_ROWS * MASK_WORDS;
    unsigned sup0 = 0, sup1 = 0;
    unsigned val0 = d_validmask[n * MASK_WORDS + lane];
    unsigned val1 = d_validmask[n * MASK_WORDS + 32 + lane];
    int count = 0;
    unsigned A0[8], A1[8], B0[8], B1[8];

    k6_load_group(maskb, lane, 0, A0, A1);
    int i0 = 0;
    while (true) {
        k6_load_group(maskb, lane, i0 + 8, B0, B1);   // prefetch (rows < 2048, padded)
        k6_proc_group(i0, lane, A0, A1, sup0, sup1, val0, val1, count, list);
        i0 += 8;
        if (count >= POST_N || i0 >= PRE_K) break;
        k6_load_group(maskb, lane, i0 + 8, A0, A1);
        k6_proc_group(i0, lane, B0, B1, sup0, sup1, val0, val1, count, list);
        i0 += 8;
        if (count >= POST_N || i0 >= PRE_K) break;
    }
    __syncwarp();

    float* o = out + (size_t)n * POST_N * 5;
    int cmax = count < POST_N ? count : POST_N;
    for (int r = lane; r < POST_N; r += 32) {
        float v0 = 0.f, v1 = 0.f, v2 = 0.f, v3 = 0.f, v4 = 0.f;
        if (r < cmax) {
            int i = list[r];
            float4 b = d_boxes[n * PRE_K + i];
            v0 = b.x; v1 = b.y; v2 = b.z; v3 = b.w;
            v4 = d_selscore[n * PRE_K + i];
        }
        o[r * 5 + 0] = v0;
        o[r * 5 + 1] = v1;
        o[r * 5 + 2] = v2;
        o[r * 5 + 3] = v3;
        o[r * 5 + 4] = v4;
    }
}

// ---------------- launch ----------------
extern "C" void kernel_launch(void* const* d_in, const int* in_sizes, int n_in,
                              void* d_out, int out_size) {
    const float* anchors = (const float*)d_in[0];   // [8, 338688, 4]
    const float* logits  = (const float*)d_in[1];   // [8, 3, 336, 336]
    const float* breg    = (const float*)d_in[2];   // [8, 12, 336, 336]
    float* out = (float*)d_out;                     // [8, 1000, 5]

    (void)in_sizes; (void)n_in; (void)out_size;

    k1_scores<<<GRID_FAT, 256>>>(logits);
    k2_thresh<<<NIMG, 256>>>();
    k3_compact<<<GRID_FAT, 256>>>();
    k4_sortdecode<<<NIMG, 1024>>>(anchors, breg);
    k5_mask<<<NIMG * ((PRE_K + RPB - 1) / RPB), 128>>>();
    k6_nms<<<NIMG, 32>>>(out);
}